// round 14
// baseline (speedup 1.0000x reference)
#include <cuda_runtime.h>

// Scratch: split-K partials [16][512*256] (8 MB) and x3 [512 x 64].
static __device__ float g_part[16][512 * 256];
static __device__ float g_x3[512 * 64];

// ---------------------------------------------------------------------------
// Kernel A1: split-K partial GEMM.  part[z] = x[32r x 32k] @ w2^T[32k x 64h]
// grid (16, 4, 16) = 1024 blocks, 128 threads, all resident.  [R8 form]
// ---------------------------------------------------------------------------
__global__ void __launch_bounds__(128) gemm1_part_kernel(
    const float* __restrict__ x,    // [512, 512]
    const float* __restrict__ w2)   // [256, 512]
{
    __shared__ float xs[32][36];
    __shared__ float ws[64][36];

    const int t  = threadIdx.x;
    const int r0 = blockIdx.x * 32;
    const int h0 = blockIdx.y * 64;
    const int k0 = blockIdx.z * 32;

    #pragma unroll
    for (int i = 0; i < 2; ++i) {
        const int idx = t + i * 128;
        const int r   = idx >> 3;
        const int kq  = (idx & 7) * 4;
        float4 v = *reinterpret_cast<const float4*>(
            x + (size_t)(r0 + r) * 512 + k0 + kq);
        *reinterpret_cast<float4*>(&xs[r][kq]) = v;
    }
    #pragma unroll
    for (int i = 0; i < 4; ++i) {
        const int idx = t + i * 128;
        const int r   = idx >> 3;
        const int kq  = (idx & 7) * 4;
        float4 v = *reinterpret_cast<const float4*>(
            w2 + (size_t)(h0 + r) * 512 + k0 + kq);
        *reinterpret_cast<float4*>(&ws[r][kq]) = v;
    }

    float acc[4][4];
    #pragma unroll
    for (int i = 0; i < 4; ++i)
        #pragma unroll
        for (int j = 0; j < 4; ++j) acc[i][j] = 0.f;

    const int tx = t & 15;
    const int ty = t >> 4;

    __syncthreads();

    #pragma unroll
    for (int kq = 0; kq < 32; kq += 4) {
        float4 a[4], bv[4];
        #pragma unroll
        for (int i = 0; i < 4; ++i)
            a[i] = *reinterpret_cast<const float4*>(&xs[ty + 8 * i][kq]);
        #pragma unroll
        for (int j = 0; j < 4; ++j)
            bv[j] = *reinterpret_cast<const float4*>(&ws[tx + 16 * j][kq]);
        #pragma unroll
        for (int i = 0; i < 4; ++i)
            #pragma unroll
            for (int j = 0; j < 4; ++j) {
                acc[i][j] = fmaf(a[i].x, bv[j].x, acc[i][j]);
                acc[i][j] = fmaf(a[i].y, bv[j].y, acc[i][j]);
                acc[i][j] = fmaf(a[i].z, bv[j].z, acc[i][j]);
                acc[i][j] = fmaf(a[i].w, bv[j].w, acc[i][j]);
            }
    }

    float* dst = g_part[blockIdx.z];
    #pragma unroll
    for (int i = 0; i < 4; ++i)
        #pragma unroll
        for (int j = 0; j < 4; ++j)
            dst[(size_t)(r0 + ty + 8 * i) * 256 + h0 + tx + 16 * j] = acc[i][j];
}

// ---------------------------------------------------------------------------
// Kernel A2 v3: parallel head.  256 blocks x 256 threads, 2 rows per block.
// ---------------------------------------------------------------------------
__global__ void __launch_bounds__(256) head_kernel(
    const float* __restrict__ b2,   // [256]
    const float* __restrict__ w3,   // [55, 256]
    const float* __restrict__ b3)   // [55]
{
    __shared__ float hs[2][260];
    __shared__ float zp[110][2];
    __shared__ float zs[2][60];

    const int t  = threadIdx.x;
    const int r0 = blockIdx.x * 2;

    if (t < 128) {
        const int i  = t >> 6;
        const int cg = t & 63;
        float4 acc = *reinterpret_cast<const float4*>(b2 + cg * 4);
        const size_t off = (size_t)(r0 + i) * 256 + cg * 4;
        #pragma unroll
        for (int z = 0; z < 16; ++z) {
            const float4 v = *reinterpret_cast<const float4*>(&g_part[z][off]);
            acc.x += v.x; acc.y += v.y; acc.z += v.z; acc.w += v.w;
        }
        acc.x = (acc.x >= 0.f) ? acc.x : 0.01f * acc.x;
        acc.y = (acc.y >= 0.f) ? acc.y : 0.01f * acc.y;
        acc.z = (acc.z >= 0.f) ? acc.z : 0.01f * acc.z;
        acc.w = (acc.w >= 0.f) ? acc.w : 0.01f * acc.w;
        *reinterpret_cast<float4*>(&hs[i][cg * 4]) = acc;
    }
    __syncthreads();

    if (t < 220) {
        const int o    = t >> 1;
        const int half = t & 1;
        const int r    = o & 1;
        const int c    = o >> 1;
        const float4* hv = reinterpret_cast<const float4*>(&hs[r][half * 128]);
        const float4* wv = reinterpret_cast<const float4*>(
            w3 + (size_t)c * 256 + half * 128);
        float acc = 0.f;
        #pragma unroll 8
        for (int k = 0; k < 32; ++k) {
            const float4 a = hv[k];
            const float4 w = __ldg(&wv[k]);
            acc = fmaf(a.x, w.x, acc); acc = fmaf(a.y, w.y, acc);
            acc = fmaf(a.z, w.z, acc); acc = fmaf(a.w, w.w, acc);
        }
        zp[o][half] = acc;
    }
    __syncthreads();

    if (t < 110) {
        const int r = t & 1;
        const int c = t >> 1;
        zs[r][c] = zp[t][0] + zp[t][1] + b3[c];
    }
    __syncthreads();

    if (t < 12) {
        const int r     = t / 6;
        const int g     = t - 6 * r;
        const int start = (g == 0) ? 0 : 5 + 10 * (g - 1);
        const int len   = (g == 0) ? 5 : 10;
        float m = -3.0e38f;
        for (int c = 0; c < len; ++c) m = fmaxf(m, zs[r][start + c]);
        float s = 0.f;
        for (int c = 0; c < len; ++c) s += __expf(zs[r][start + c] - m);
        const float inv = 1.0f / s;
        float* dst = &g_x3[(size_t)(r0 + r) * 64];
        for (int c = 0; c < len; ++c)
            dst[start + c] = __expf(zs[r][start + c] - m) * inv;
    }
}

// ---------------------------------------------------------------------------
// Kernel B: expansion, 4 rows per block.
//
// Rows g, g+128, g+256, g+384 share pad = g & 3 (128 % 4 == 0), so the
// loop-invariant run phase (rt/rem/c1..c3) is shared across the 4 rows.
// Phase 1 computes the digit indices ONCE per run and applies them to all
// 4 rows' p-tables. grid (8, 128) = 1024 blocks, 640 threads.
// ---------------------------------------------------------------------------
__global__ void __launch_bounds__(640) expand_kernel(float* __restrict__ out)
{
    __shared__ float ps[4][64];      // p tables for the 4 rows
    __shared__ float sv[4][1284];    // run values per row

    const unsigned t   = threadIdx.x;
    const unsigned bx  = blockIdx.x;
    const unsigned g   = blockIdx.y;        // row group
    const unsigned pad = g & 3u;
    const unsigned rbase = bx * 1280u;      // multiple of 10

    // load 4 p-tables (rows g + 128*m)
    if (t < 256u) {
        const unsigned m   = t >> 6;
        const unsigned idx = t & 63u;
        ps[m][idx] = g_x3[(size_t)(g + 128u * m) * 64u + idx];
    }
    __syncthreads();

    // --- phase 1: run values for runs [rbase, rbase + 1282), 4 rows ---
    #pragma unroll
    for (unsigned kk = 0; kk < 3u; ++kk) {
        const unsigned ri = t + kk * 640u;
        if (ri < 1282u) {
            const unsigned r = rbase + ri;
            if (r == 0u) {
                #pragma unroll
                for (int m = 0; m < 4; ++m) sv[m][ri] = ps[m][0];
            } else if (r < 10u) {
                const unsigned i1 = 5u + r;
                #pragma unroll
                for (int m = 0; m < 4; ++m) sv[m][ri] = ps[m][1] * ps[m][i1];
            } else if (r < 100u) {
                const unsigned q1 = r / 10u;
                const unsigned i1 = 5u + q1, i2 = 15u + (r - 10u * q1);
                #pragma unroll
                for (int m = 0; m < 4; ++m)
                    sv[m][ri] = ps[m][2] * ps[m][i1] * ps[m][i2];
            } else if (r < 1000u) {
                const unsigned q1 = r / 10u, q2 = r / 100u;
                const unsigned i1 = 5u + q2, i2 = 15u + (q1 - 10u * q2),
                               i3 = 25u + (r - 10u * q1);
                #pragma unroll
                for (int m = 0; m < 4; ++m)
                    sv[m][ri] = ps[m][3] * ps[m][i1] * ps[m][i2] * ps[m][i3];
            } else if (r < 10000u) {
                const unsigned q1 = r / 10u, q2 = r / 100u, q3 = r / 1000u;
                const unsigned i1 = 5u + q3, i2 = 15u + (q2 - 10u * q3),
                               i3 = 25u + (q1 - 10u * q2),
                               i4 = 35u + (r - 10u * q1);
                #pragma unroll
                for (int m = 0; m < 4; ++m)
                    sv[m][ri] = ps[m][4] * ps[m][i1] * ps[m][i2]
                              * ps[m][i3] * ps[m][i4];
            } else {
                #pragma unroll
                for (int m = 0; m < 4; ++m) sv[m][ri] = 0.f;
            }
        }
    }
    __syncthreads();

    // --- phase 2: stores, 4 rows x 5 iterations ---
    const unsigned ph  = pad + 4u * t;      // < 2563
    const unsigned rt  = ph / 10u;
    const unsigned rem = ph - 10u * rt;
    const bool c1 = (rem + 1u < 10u);
    const bool c2 = (rem + 2u < 10u);
    const bool c3 = (rem + 3u < 10u);

    float* o[4];
    float4* ov[4];
    #pragma unroll
    for (int m = 0; m < 4; ++m) {
        o[m]  = out + (size_t)(g + 128u * m) * 99999u;
        ov[m] = reinterpret_cast<float4*>(o[m] + pad);   // 16B-aligned
    }

    if (bx < 7u) {
        #pragma unroll
        for (int k = 0; k < 5; ++k) {
            const unsigned vi = bx * 3200u + t + (unsigned)k * 640u;
            const unsigned ri = rt + (unsigned)k * 256u;
            #pragma unroll
            for (int m = 0; m < 4; ++m) {
                const float f0 = sv[m][ri];
                const float f1 = sv[m][ri + 1u];
                float4 w;
                w.x = f0;
                w.y = c1 ? f0 : f1;
                w.z = c2 ? f0 : f1;
                w.w = c3 ? f0 : f1;
                __stcs(&ov[m][vi], w);
            }
        }
        // head scalars + patch out[b, 0]
        if (bx == 0u) {
            if (t == 0u) {
                #pragma unroll
                for (int m = 0; m < 4; ++m) o[m][0] = ps[m][1] * ps[m][5];
            } else if (t < pad) {
                #pragma unroll
                for (int m = 0; m < 4; ++m) o[m][t] = ps[m][0];
            }
        }
    } else {
        // bx == 7: float4 indices [22400, 24999), guarded
        #pragma unroll
        for (int k = 0; k < 5; ++k) {
            const unsigned vi = 22400u + t + (unsigned)k * 640u;
            if (vi < 24999u) {
                const unsigned ri = rt + (unsigned)k * 256u;
                #pragma unroll
                for (int m = 0; m < 4; ++m) {
                    const float f0 = sv[m][ri];
                    const float f1 = sv[m][ri + 1u];
                    float4 w;
                    w.x = f0;
                    w.y = c1 ? f0 : f1;
                    w.z = c2 ? f0 : f1;
                    w.w = c3 ? f0 : f1;
                    __stcs(&ov[m][vi], w);
                }
            }
        }
        // scalar tail: i in [pad + 99996, 99999), run 9999 = rbase + 1039
        if (t < 3u - pad) {
            #pragma unroll
            for (int m = 0; m < 4; ++m)
                o[m][pad + 99996u + t] = sv[m][1039];
        }
    }
}

// ---------------------------------------------------------------------------
extern "C" void kernel_launch(void* const* d_in, const int* in_sizes, int n_in,
                              void* d_out, int out_size)
{
    (void)in_sizes; (void)n_in; (void)out_size;
    const float* x  = (const float*)d_in[0];   // [512, 512]
    const float* w2 = (const float*)d_in[1];   // [256, 512]
    const float* b2 = (const float*)d_in[2];   // [256]
    const float* w3 = (const float*)d_in[3];   // [55, 256]
    const float* b3 = (const float*)d_in[4];   // [55]
    float* out = (float*)d_out;                // [512, 99999]

    gemm1_part_kernel<<<dim3(16, 4, 16), 128>>>(x, w2);
    head_kernel<<<256, 256>>>(b2, w3, b3);
    expand_kernel<<<dim3(8, 128), 640>>>(out);
}